// round 12
// baseline (speedup 1.0000x reference)
#include <cuda_runtime.h>
#include <cuda_fp16.h>
#include <cstdint>

#define Bsz  64
#define Csz  256
#define HW   1024
#define CTR  528        // 16*32 + 16
#define KC   32         // K chunk (= 16 fp16x2 k-pairs)
#define NCH  8          // 256 / 32
#define SA2  264        // A smem k2-row stride (u32): 256 + 8
#define SB2  72         // B smem k2-row stride (u32): 64 + 8
#define BUFA (16 * SA2) // 4224 u32
#define BUFB (16 * SB2) // 1152 u32

// per-CTA partials, S/P interleaved, slot-innermost: [z][o][slot]
__device__ float2 g_SP[2 * Bsz][Csz][16];
// completion counters per batch (32 CTAs each); self-resetting
__device__ int g_cnt[Bsz];

// transposed weights; per-z folded A operand packed as fp16x2 over k-pairs
__device__ float    g_Wt[257][Csz];
__device__ uint32_t g_Wzh[2 * Bsz][Csz / 2][Csz];   // 16.8 MB (L2-resident)

__device__ __forceinline__ uint32_t packf16(float lo, float hi) {
    uint32_t d;
    asm("cvt.rn.f16x2.f32 %0, %1, %2;" : "=r"(d) : "f"(hi), "f"(lo));
    return d;
}

__device__ __forceinline__ void mma16(float* c, const uint32_t* a,
                                      uint32_t b0, uint32_t b1) {
    asm volatile(
        "mma.sync.aligned.m16n8k16.row.col.f32.f16.f16.f32 "
        "{%0,%1,%2,%3}, {%4,%5,%6,%7}, {%8,%9}, {%0,%1,%2,%3};"
        : "+f"(c[0]), "+f"(c[1]), "+f"(c[2]), "+f"(c[3])
        : "r"(a[0]), "r"(a[1]), "r"(a[2]), "r"(a[3]), "r"(b0), "r"(b1));
}

__device__ __forceinline__ uint32_t smem_u32(const void* p) {
    uint32_t a;
    asm("{ .reg .u64 t; cvta.to.shared.u64 t, %1; cvt.u32.u64 %0, t; }" : "=r"(a) : "l"(p));
    return a;
}

// ---------------------------------------------------------------------------
// prep 1: Wt[k][m] = W[m][k]
// ---------------------------------------------------------------------------
__global__ void transpose_w(const float* __restrict__ w) {
    int k = blockIdx.x;          // 0..256
    int m = threadIdx.x;         // 0..255
    g_Wt[k][m] = w[(size_t)m * 257 + k];
}

// ---------------------------------------------------------------------------
// prep 2: Wzh[z][k2][m] = fp16x2 of the two folded k values
// ---------------------------------------------------------------------------
__global__ void __launch_bounds__(1024) build_wzh(const float* __restrict__ x1,
                                                  const float* __restrict__ x2) {
    const int z = blockIdx.y;
    const int branch = z >> 6, b = z & 63;
    const float* xz = (branch ? x2 : x1) + (size_t)b * Csz * HW;

    int idx = blockIdx.x * 1024 + threadIdx.x;
    int m = idx & 255;
    int k2 = idx >> 8;                            // 0..127
    float cen0 = xz[(size_t)(2 * k2) * HW + CTR] * (1.0f / 256.0f);
    float cen1 = xz[(size_t)(2 * k2 + 1) * HW + CTR] * (1.0f / 256.0f);
    float wc = g_Wt[256][m];
    float v0 = g_Wt[2 * k2][m] + wc * cen0;
    float v1 = g_Wt[2 * k2 + 1][m] + wc * cen1;
    g_Wzh[z][k2][m] = packf16(v0, v1);
}

// ---------------------------------------------------------------------------
// main GEMM (fp16 in, fp32 acc) + fused sigmoid-pool + last-CTA finalize
// grid (16 n-tiles, 128 z), block 256 (8 warps = 8M x 1N; warp tile 32 x 64)
// ---------------------------------------------------------------------------
__global__ void __launch_bounds__(256, 2)
gemm_pool_kernel(const float* __restrict__ x1, const float* __restrict__ x2,
                 float* __restrict__ out) {
    extern __shared__ uint32_t sm[];
    __shared__ int s_win;
    uint32_t* Ab[2] = { sm, sm + BUFA };
    uint32_t* Bb[2] = { sm + 2 * BUFA, sm + 2 * BUFA + BUFB };
    uint32_t* stash = sm + 2 * BUFA + 2 * BUFB;   // 128 k2-rows x SB2

    const int tid = threadIdx.x;
    const int z = blockIdx.y;
    const int branch = z >> 6, b = z & 63;
    const float* xz = (branch ? x2 : x1) + (size_t)b * Csz * HW;
    const int n0 = blockIdx.x * 64;
    const uint32_t* wzh = &g_Wzh[z][0][0];        // [128 k2][256 m]

    const uint32_t sA0 = smem_u32(Ab[0]);
    const uint32_t sA1 = smem_u32(Ab[1]);

    float4 Brf0, Brf1;

#define CPA(kc, sbase) { _Pragma("unroll") for (int q = 0; q < 4; ++q) {       \
        int idx = tid + q * 256;                                               \
        uint32_t dst = (sbase) + ((idx >> 6) * SA2 + (idx & 63) * 4) * 4;      \
        const uint32_t* src = wzh + (size_t)((kc) * 16 + (idx >> 6)) * 256     \
                              + (idx & 63) * 4;                                \
        asm volatile("cp.async.cg.shared.global [%0], [%1], 16;"               \
                     :: "r"(dst), "l"(src)); }                                 \
    asm volatile("cp.async.commit_group;"); }
#define LD_B(kc) {                                                             \
        const float* p0 = xz + (size_t)((kc) * KC + 2 * (tid >> 4)) * HW       \
                          + n0 + (tid & 15) * 4;                               \
        Brf0 = *(const float4*)p0;                                             \
        Brf1 = *(const float4*)(p0 + HW); }
#define ST_B(buf, kc) {                                                        \
        uint4 v;                                                               \
        v.x = packf16(Brf0.x, Brf1.x);                                         \
        v.y = packf16(Brf0.y, Brf1.y);                                         \
        v.z = packf16(Brf0.z, Brf1.z);                                         \
        v.w = packf16(Brf0.w, Brf1.w);                                         \
        *(uint4*)(Bb[buf] + (tid >> 4) * SB2 + (tid & 15) * 4) = v;            \
        *(uint4*)(stash + ((kc) * 16 + (tid >> 4)) * SB2 + (tid & 15) * 4) = v; }

    // ---- MMA mapping: 8 warps stacked in M; warp tile 32 x 64
    const int lane = tid & 31;
    const int wid = tid >> 5;
    const int wm = wid * 32;
    const int g = lane >> 2, tg = lane & 3;

    float acc[2][8][4];
#pragma unroll
    for (int i = 0; i < 2; ++i)
#pragma unroll
        for (int j = 0; j < 8; ++j)
#pragma unroll
            for (int r = 0; r < 4; ++r) acc[i][j][r] = 0.0f;

    CPA(0, sA0); LD_B(0); ST_B(0, 0);
    asm volatile("cp.async.wait_group 0;");
    __syncthreads();

#pragma unroll
    for (int kc = 0; kc < NCH; ++kc) {
        const int buf = kc & 1;
        if (kc < NCH - 1) { CPA(kc + 1, buf ? sA0 : sA1); LD_B(kc + 1); }

        const uint32_t* A = Ab[buf];
        const uint32_t* B = Bb[buf];
#pragma unroll
        for (int ks = 0; ks < 2; ++ks) {
            const int ko = ks * 8;                 // k2 offset (8 pairs = k16)
            uint32_t a[2][4];
#pragma unroll
            for (int i = 0; i < 2; ++i) {
                const int rb = wm + i * 16 + g;
                a[i][0] = A[(ko + tg) * SA2 + rb];
                a[i][1] = A[(ko + tg) * SA2 + rb + 8];
                a[i][2] = A[(ko + tg + 4) * SA2 + rb];
                a[i][3] = A[(ko + tg + 4) * SA2 + rb + 8];
            }
#pragma unroll
            for (int j = 0; j < 8; ++j) {
                const int cb = j * 8 + g;
                uint32_t b0 = B[(ko + tg) * SB2 + cb];
                uint32_t b1 = B[(ko + tg + 4) * SB2 + cb];
#pragma unroll
                for (int i = 0; i < 2; ++i) mma16(acc[i][j], a[i], b0, b1);
            }
        }
        if (kc < NCH - 1) {
            ST_B(buf ^ 1, kc + 1);
            asm volatile("cp.async.wait_group 0;");
        }
        __syncthreads();
    }

    // ---- fused epilogue: sigmoid + pooled partials; x from fp16 stash
#pragma unroll
    for (int i = 0; i < 2; ++i) {
#pragma unroll
        for (int rs = 0; rs < 2; ++rs) {
            const int lrow = wm + i * 16 + g + rs * 8;      // 0..255
            const int k2L = lrow >> 1, h = lrow & 1;
            const uint32_t* srow = stash + k2L * SB2 + 2 * tg;
            float sS = 0.0f, sP = 0.0f;
#pragma unroll
            for (int j = 0; j < 8; ++j) {
                uint2 u = *(const uint2*)(srow + j * 8);
                __half2 p0 = *reinterpret_cast<__half2*>(&u.x);
                __half2 p1 = *reinterpret_cast<__half2*>(&u.y);
                float xv0 = h ? __high2float(p0) : __low2float(p0);
                float xv1 = h ? __high2float(p1) : __low2float(p1);
                float v0 = acc[i][j][2 * rs];
                float v1 = acc[i][j][2 * rs + 1];
                float s0 = __fdividef(1.0f, 1.0f + __expf(-v0));
                float s1 = __fdividef(1.0f, 1.0f + __expf(-v1));
                sS += s0 + s1;
                sP += s0 * xv0 + s1 * xv1;
            }
            sS += __shfl_xor_sync(0xffffffffu, sS, 1);
            sS += __shfl_xor_sync(0xffffffffu, sS, 2);
            sP += __shfl_xor_sync(0xffffffffu, sP, 1);
            sP += __shfl_xor_sync(0xffffffffu, sP, 2);
            if (tg == 0)
                g_SP[z][lrow][blockIdx.x] = make_float2(sS, sP);
        }
    }

    // ---- last-CTA-per-batch reduction (replaces the finalize kernel)
    __threadfence();
    __syncthreads();
    if (tid == 0) {
        int old = atomicAdd(&g_cnt[b], 1);
        s_win = (old == 31);
    }
    __syncthreads();
    if (s_win) {
        __threadfence();                 // see all 32 CTAs' g_SP writes
        const int o = tid;               // 0..255
        float r = 0.0f;
#pragma unroll
        for (int br = 0; br < 2; ++br) {
            const float2* p = g_SP[br * Bsz + b][o];
            float S = 0.0f, P = 0.0f;
#pragma unroll
            for (int s = 0; s < 16; ++s) {
                float2 v = p[s];
                S += v.x;
                P += v.y;
            }
            r += P / (S + 1e-8f);
        }
        out[b * 256 + o] = r;
        if (tid == 0) g_cnt[b] = 0;      // self-reset for next graph replay
    }
}

// ---------------------------------------------------------------------------
extern "C" void kernel_launch(void* const* d_in, const int* in_sizes, int n_in,
                              void* d_out, int out_size) {
    const float* x1 = (const float*)d_in[0];
    const float* x2 = (const float*)d_in[1];
    const float* w  = (const float*)d_in[2];
    // d_in[3..6] (ca_*) are mathematically unused: softmax over a size-1 axis == 1.
    float* out = (float*)d_out;

    constexpr int SMEM_SZ = (2 * BUFA + 2 * BUFB + 128 * SB2) * 4;   // 79872 B
    cudaFuncSetAttribute(gemm_pool_kernel,
                         cudaFuncAttributeMaxDynamicSharedMemorySize, SMEM_SZ);

    transpose_w<<<257, 256>>>(w);
    build_wzh<<<dim3(32, 2 * Bsz), 1024>>>(x1, x2);
    gemm_pool_kernel<<<dim3(16, 2 * Bsz), 256, SMEM_SZ>>>(x1, x2, out);
}

// round 13
// speedup vs baseline: 1.0300x; 1.0300x over previous
#include <cuda_runtime.h>
#include <cuda_fp16.h>
#include <cstdint>

#define Bsz  64
#define Csz  256
#define HW   1024
#define CTR  528        // 16*32 + 16
#define KC   32         // K chunk (= 16 fp16x2 k-pairs)
#define NCH  8          // 256 / 32
#define SA2  264        // A smem k2-row stride (u32): 256 + 8
#define SB2  72         // B smem k2-row stride (u32): 64 + 8
#define BUFA (16 * SA2) // 4224 u32
#define BUFB (16 * SB2) // 1152 u32

// smem layout (u32 offsets)
#define OFF_B    (2 * BUFA)              // 8448
#define OFF_ST   (2 * BUFA + 2 * BUFB)   // 10752
#define OFF_CEN  (OFF_ST + 128 * SB2)    // 19968
#define OFF_WL   (OFF_CEN + 256)         // 20224
#define OFF_DOT  (OFF_WL + 256)          // 20480
#define SMEM_U32 (OFF_DOT + 64)          // 20544 -> 82176 B

// per-CTA partials, S/P interleaved, slot-innermost: [z][o][slot]
__device__ float2 g_SP[2 * Bsz][Csz][16];
// z-independent transposed fp16x2 weights: [k2][m]
__device__ uint32_t g_Wth[Csz / 2][Csz];   // 128 KB

__device__ __forceinline__ uint32_t packf16(float lo, float hi) {
    uint32_t d;
    asm("cvt.rn.f16x2.f32 %0, %1, %2;" : "=r"(d) : "f"(hi), "f"(lo));
    return d;
}

__device__ __forceinline__ void mma16(float* c, const uint32_t* a,
                                      uint32_t b0, uint32_t b1) {
    asm volatile(
        "mma.sync.aligned.m16n8k16.row.col.f32.f16.f16.f32 "
        "{%0,%1,%2,%3}, {%4,%5,%6,%7}, {%8,%9}, {%0,%1,%2,%3};"
        : "+f"(c[0]), "+f"(c[1]), "+f"(c[2]), "+f"(c[3])
        : "r"(a[0]), "r"(a[1]), "r"(a[2]), "r"(a[3]), "r"(b0), "r"(b1));
}

__device__ __forceinline__ uint32_t smem_u32(const void* p) {
    uint32_t a;
    asm("{ .reg .u64 t; cvta.to.shared.u64 t, %1; cvt.u32.u64 %0, t; }" : "=r"(a) : "l"(p));
    return a;
}

// ---------------------------------------------------------------------------
// prep: Wth[k2][m] = fp16x2(W[m][2k2], W[m][2k2+1])   (z-independent, tiny)
// grid 128 (k2), block 256 (m)
// ---------------------------------------------------------------------------
__global__ void build_wth(const float* __restrict__ w) {
    int k2 = blockIdx.x;
    int m = threadIdx.x;
    const float* wr = w + (size_t)m * 257 + 2 * k2;
    g_Wth[k2][m] = packf16(wr[0], wr[1]);
}

// ---------------------------------------------------------------------------
// main GEMM (fp16 in, fp32 acc) + in-loop dot GEMV + fused sigmoid-pool
// grid (16 n-tiles, 128 z), block 256 (8 warps = 8M x 1N; warp tile 32 x 64)
// v[o,n] = (W.x)[o,n] + wl[o]*dot[n]; dot accumulated in fp32 during staging.
// ---------------------------------------------------------------------------
__global__ void __launch_bounds__(256, 2)
gemm_pool_kernel(const float* __restrict__ x1, const float* __restrict__ x2,
                 const float* __restrict__ w) {
    extern __shared__ uint32_t sm[];
    uint32_t* Ab[2] = { sm, sm + BUFA };
    uint32_t* Bb[2] = { sm + OFF_B, sm + OFF_B + BUFB };
    uint32_t* stash = sm + OFF_ST;                // 128 k2-rows x SB2
    float* cen_sm = (float*)(sm + OFF_CEN);       // cen[c]/256
    float* wl_sm  = (float*)(sm + OFF_WL);        // W[o][256]
    float* dot_sm = (float*)(sm + OFF_DOT);       // dot[n], 64

    const int tid = threadIdx.x;
    const int z = blockIdx.y;
    const int branch = z >> 6, b = z & 63;
    const float* xz = (branch ? x2 : x1) + (size_t)b * Csz * HW;
    const int n0 = blockIdx.x * 64;

    const uint32_t sA0 = smem_u32(Ab[0]);
    const uint32_t sA1 = smem_u32(Ab[1]);

    // stage cen (fp32, /256) and wl; zero dot accumulator
    cen_sm[tid] = xz[(size_t)tid * HW + CTR] * (1.0f / 256.0f);
    wl_sm[tid] = w[(size_t)tid * 257 + 256];
    if (tid < 64) dot_sm[tid] = 0.0f;
    __syncthreads();

    float4 Brf0, Brf1;
    float pd[4] = {0.0f, 0.0f, 0.0f, 0.0f};      // per-thread dot partials

#define CPA(kc, sbase) { _Pragma("unroll") for (int q = 0; q < 4; ++q) {       \
        int idx = tid + q * 256;                                               \
        uint32_t dst = (sbase) + ((idx >> 6) * SA2 + (idx & 63) * 4) * 4;      \
        const uint32_t* src = &g_Wth[(kc) * 16 + (idx >> 6)][(idx & 63) * 4];  \
        asm volatile("cp.async.cg.shared.global [%0], [%1], 16;"               \
                     :: "r"(dst), "l"(src)); }                                 \
    asm volatile("cp.async.commit_group;"); }
#define LD_B(kc) {                                                             \
        const float* p0 = xz + (size_t)((kc) * KC + 2 * (tid >> 4)) * HW       \
                          + n0 + (tid & 15) * 4;                               \
        Brf0 = *(const float4*)p0;                                             \
        Brf1 = *(const float4*)(p0 + HW); }
#define ST_B(buf, kc) {                                                        \
        float c0 = cen_sm[(kc) * KC + 2 * (tid >> 4)];                         \
        float c1 = cen_sm[(kc) * KC + 2 * (tid >> 4) + 1];                     \
        pd[0] += Brf0.x * c0 + Brf1.x * c1;                                    \
        pd[1] += Brf0.y * c0 + Brf1.y * c1;                                    \
        pd[2] += Brf0.z * c0 + Brf1.z * c1;                                    \
        pd[3] += Brf0.w * c0 + Brf1.w * c1;                                    \
        uint4 v;                                                               \
        v.x = packf16(Brf0.x, Brf1.x);                                         \
        v.y = packf16(Brf0.y, Brf1.y);                                         \
        v.z = packf16(Brf0.z, Brf1.z);                                         \
        v.w = packf16(Brf0.w, Brf1.w);                                         \
        *(uint4*)(Bb[buf] + (tid >> 4) * SB2 + (tid & 15) * 4) = v;            \
        *(uint4*)(stash + ((kc) * 16 + (tid >> 4)) * SB2 + (tid & 15) * 4) = v; }

    // ---- MMA mapping: 8 warps stacked in M; warp tile 32 x 64
    const int lane = tid & 31;
    const int wid = tid >> 5;
    const int wm = wid * 32;
    const int g = lane >> 2, tg = lane & 3;

    float acc[2][8][4];
#pragma unroll
    for (int i = 0; i < 2; ++i)
#pragma unroll
        for (int j = 0; j < 8; ++j)
#pragma unroll
            for (int r = 0; r < 4; ++r) acc[i][j][r] = 0.0f;

    CPA(0, sA0); LD_B(0); ST_B(0, 0);
    asm volatile("cp.async.wait_group 0;");
    __syncthreads();

#pragma unroll
    for (int kc = 0; kc < NCH; ++kc) {
        const int buf = kc & 1;
        if (kc < NCH - 1) { CPA(kc + 1, buf ? sA0 : sA1); LD_B(kc + 1); }

        const uint32_t* A = Ab[buf];
        const uint32_t* B = Bb[buf];
#pragma unroll
        for (int ks = 0; ks < 2; ++ks) {
            const int ko = ks * 8;                 // k2 offset (8 pairs = k16)
            uint32_t a[2][4];
#pragma unroll
            for (int i = 0; i < 2; ++i) {
                const int rb = wm + i * 16 + g;
                a[i][0] = A[(ko + tg) * SA2 + rb];
                a[i][1] = A[(ko + tg) * SA2 + rb + 8];
                a[i][2] = A[(ko + tg + 4) * SA2 + rb];
                a[i][3] = A[(ko + tg + 4) * SA2 + rb + 8];
            }
#pragma unroll
            for (int j = 0; j < 8; ++j) {
                const int cb = j * 8 + g;
                uint32_t b0 = B[(ko + tg) * SB2 + cb];
                uint32_t b1 = B[(ko + tg + 4) * SB2 + cb];
#pragma unroll
                for (int i = 0; i < 2; ++i) mma16(acc[i][j], a[i], b0, b1);
            }
        }
        if (kc < NCH - 1) {
            ST_B(buf ^ 1, kc + 1);
            asm volatile("cp.async.wait_group 0;");
        }
        __syncthreads();
    }

    // flush dot partials (fp32) and make dot[n] visible
#pragma unroll
    for (int j = 0; j < 4; ++j)
        atomicAdd(&dot_sm[(tid & 15) * 4 + j], pd[j]);
    __syncthreads();

    // ---- fused epilogue: rank-1 update + sigmoid + pooled partials
#pragma unroll
    for (int i = 0; i < 2; ++i) {
#pragma unroll
        for (int rs = 0; rs < 2; ++rs) {
            const int lrow = wm + i * 16 + g + rs * 8;      // 0..255
            const int k2L = lrow >> 1, h = lrow & 1;
            const uint32_t* srow = stash + k2L * SB2 + 2 * tg;
            const float wl = wl_sm[lrow];
            float sS = 0.0f, sP = 0.0f;
#pragma unroll
            for (int j = 0; j < 8; ++j) {
                uint2 u = *(const uint2*)(srow + j * 8);
                __half2 p0 = *reinterpret_cast<__half2*>(&u.x);
                __half2 p1 = *reinterpret_cast<__half2*>(&u.y);
                float xv0 = h ? __high2float(p0) : __low2float(p0);
                float xv1 = h ? __high2float(p1) : __low2float(p1);
                float v0 = acc[i][j][2 * rs] + wl * dot_sm[j * 8 + 2 * tg];
                float v1 = acc[i][j][2 * rs + 1] + wl * dot_sm[j * 8 + 2 * tg + 1];
                float s0 = __fdividef(1.0f, 1.0f + __expf(-v0));
                float s1 = __fdividef(1.0f, 1.0f + __expf(-v1));
                sS += s0 + s1;
                sP += s0 * xv0 + s1 * xv1;
            }
            sS += __shfl_xor_sync(0xffffffffu, sS, 1);
            sS += __shfl_xor_sync(0xffffffffu, sS, 2);
            sP += __shfl_xor_sync(0xffffffffu, sP, 1);
            sP += __shfl_xor_sync(0xffffffffu, sP, 2);
            if (tg == 0)
                g_SP[z][lrow][blockIdx.x] = make_float2(sS, sP);
        }
    }
}

// ---------------------------------------------------------------------------
// finalize: 8 threads per output; coalesced float2 reads (32B/thread);
// per-branch divide, then cross-branch add. grid 512 x block 256.
// ---------------------------------------------------------------------------
__global__ void finalize_kernel(float* __restrict__ out) {
    const int tid = threadIdx.x;
    const int i = blockIdx.x * 32 + (tid >> 3);   // output index (b*256+o)
    const int part = tid & 7;                      // br = part>>2, quarter = part&3
    const int b = i >> 8, o = i & 255;
    const int br = part >> 2;
    const int z = br * Bsz + b;
    const int s0 = (part & 3) * 4;

    const float2* p = &g_SP[z][o][s0];
    float2 v0 = p[0], v1 = p[1], v2 = p[2], v3 = p[3];
    float S = (v0.x + v1.x) + (v2.x + v3.x);
    float P = (v0.y + v1.y) + (v2.y + v3.y);
    // reduce the 4 quarters within each branch (lanes differ in bits 0..1)
    S += __shfl_xor_sync(0xffffffffu, S, 1);
    P += __shfl_xor_sync(0xffffffffu, P, 1);
    S += __shfl_xor_sync(0xffffffffu, S, 2);
    P += __shfl_xor_sync(0xffffffffu, P, 2);
    float r = P / (S + 1e-8f);
    // add the two branches (lanes differ in bit 2)
    r += __shfl_xor_sync(0xffffffffu, r, 4);
    if (part == 0) out[i] = r;
}

// ---------------------------------------------------------------------------
extern "C" void kernel_launch(void* const* d_in, const int* in_sizes, int n_in,
                              void* d_out, int out_size) {
    const float* x1 = (const float*)d_in[0];
    const float* x2 = (const float*)d_in[1];
    const float* w  = (const float*)d_in[2];
    // d_in[3..6] (ca_*) are mathematically unused: softmax over a size-1 axis == 1.
    float* out = (float*)d_out;

    constexpr int SMEM_SZ = SMEM_U32 * 4;          // 82176 B
    cudaFuncSetAttribute(gemm_pool_kernel,
                         cudaFuncAttributeMaxDynamicSharedMemorySize, SMEM_SZ);

    build_wth<<<128, 256>>>(w);
    gemm_pool_kernel<<<dim3(16, 2 * Bsz), 256, SMEM_SZ>>>(x1, x2, w);
    finalize_kernel<<<512, 256>>>(out);
}

// round 14
// speedup vs baseline: 1.1172x; 1.0846x over previous
#include <cuda_runtime.h>
#include <cuda_fp16.h>
#include <cstdint>

#define Bsz  64
#define Csz  256
#define HW   1024
#define CTR  528        // 16*32 + 16
#define KC   32         // K chunk (= 16 fp16x2 k-pairs)
#define NCH  8          // 256 / 32
#define SA2  264        // A smem k2-row stride (u32): 256 + 8
#define SB2  72         // B smem k2-row stride (u32): 64 + 8
#define BUFA (16 * SA2) // 4224 u32
#define BUFB (16 * SB2) // 1152 u32

// per-CTA partials, S/P interleaved, slot-innermost: [z][o][slot]
__device__ float2 g_SP[2 * Bsz][Csz][16];

// transposed weights; per-z folded A operand packed as fp16x2 over k-pairs
__device__ float    g_Wt[257][Csz];
__device__ uint32_t g_Wzh[2 * Bsz][Csz / 2][Csz];   // 16.8 MB (L2-resident)

__device__ __forceinline__ uint32_t packf16(float lo, float hi) {
    uint32_t d;
    asm("cvt.rn.f16x2.f32 %0, %1, %2;" : "=r"(d) : "f"(hi), "f"(lo));
    return d;
}

__device__ __forceinline__ void mma16(float* c, const uint32_t* a,
                                      uint32_t b0, uint32_t b1) {
    asm volatile(
        "mma.sync.aligned.m16n8k16.row.col.f32.f16.f16.f32 "
        "{%0,%1,%2,%3}, {%4,%5,%6,%7}, {%8,%9}, {%0,%1,%2,%3};"
        : "+f"(c[0]), "+f"(c[1]), "+f"(c[2]), "+f"(c[3])
        : "r"(a[0]), "r"(a[1]), "r"(a[2]), "r"(a[3]), "r"(b0), "r"(b1));
}

__device__ __forceinline__ uint32_t smem_u32(const void* p) {
    uint32_t a;
    asm("{ .reg .u64 t; cvta.to.shared.u64 t, %1; cvt.u32.u64 %0, t; }" : "=r"(a) : "l"(p));
    return a;
}

// ---------------------------------------------------------------------------
// prep 1: Wt[k][m] = W[m][k]  (64 blocks x 1024 threads; 4 k-rows per block)
// ---------------------------------------------------------------------------
__global__ void __launch_bounds__(1024) transpose_w(const float* __restrict__ w) {
    int idx = blockIdx.x * 1024 + threadIdx.x;    // 0..65535
    int k = idx >> 8;                              // 0..255
    int m = idx & 255;
    g_Wt[k][m] = w[(size_t)m * 257 + k];
    if (idx < 256) g_Wt[256][idx] = w[(size_t)idx * 257 + 256];
}

// ---------------------------------------------------------------------------
// prep 2: Wzh[z][k2][m] = fp16x2 of the two folded k values
// ---------------------------------------------------------------------------
__global__ void __launch_bounds__(1024) build_wzh(const float* __restrict__ x1,
                                                  const float* __restrict__ x2) {
    const int z = blockIdx.y;
    const int branch = z >> 6, b = z & 63;
    const float* xz = (branch ? x2 : x1) + (size_t)b * Csz * HW;

    int idx = blockIdx.x * 1024 + threadIdx.x;
    int m = idx & 255;
    int k2 = idx >> 8;                            // 0..127
    float cen0 = xz[(size_t)(2 * k2) * HW + CTR] * (1.0f / 256.0f);
    float cen1 = xz[(size_t)(2 * k2 + 1) * HW + CTR] * (1.0f / 256.0f);
    float wc = g_Wt[256][m];
    float v0 = g_Wt[2 * k2][m] + wc * cen0;
    float v1 = g_Wt[2 * k2 + 1][m] + wc * cen1;
    g_Wzh[z][k2][m] = packf16(v0, v1);
}

// ---------------------------------------------------------------------------
// main GEMM (fp16 in, fp32 acc) + fused sigmoid-pool  (R11 inner loop, verbatim)
// grid (16 n-tiles, 128 z), block 256 (8 warps = 8M x 1N; warp tile 32 x 64)
// ---------------------------------------------------------------------------
__global__ void __launch_bounds__(256, 2)
gemm_pool_kernel(const float* __restrict__ x1, const float* __restrict__ x2) {
    extern __shared__ uint32_t sm[];
    uint32_t* Ab[2] = { sm, sm + BUFA };
    uint32_t* Bb[2] = { sm + 2 * BUFA, sm + 2 * BUFA + BUFB };
    uint32_t* stash = sm + 2 * BUFA + 2 * BUFB;   // 128 k2-rows x SB2

    const int tid = threadIdx.x;
    const int z = blockIdx.y;
    const int branch = z >> 6, b = z & 63;
    const float* xz = (branch ? x2 : x1) + (size_t)b * Csz * HW;
    const int n0 = blockIdx.x * 64;
    const uint32_t* wzh = &g_Wzh[z][0][0];        // [128 k2][256 m]

    const uint32_t sA0 = smem_u32(Ab[0]);
    const uint32_t sA1 = smem_u32(Ab[1]);

    float4 Brf0, Brf1;

#define CPA(kc, sbase) { _Pragma("unroll") for (int q = 0; q < 4; ++q) {       \
        int idx = tid + q * 256;                                               \
        uint32_t dst = (sbase) + ((idx >> 6) * SA2 + (idx & 63) * 4) * 4;      \
        const uint32_t* src = wzh + (size_t)((kc) * 16 + (idx >> 6)) * 256     \
                              + (idx & 63) * 4;                                \
        asm volatile("cp.async.cg.shared.global [%0], [%1], 16;"               \
                     :: "r"(dst), "l"(src)); }                                 \
    asm volatile("cp.async.commit_group;"); }
#define LD_B(kc) {                                                             \
        const float* p0 = xz + (size_t)((kc) * KC + 2 * (tid >> 4)) * HW       \
                          + n0 + (tid & 15) * 4;                               \
        Brf0 = *(const float4*)p0;                                             \
        Brf1 = *(const float4*)(p0 + HW); }
#define ST_B(buf, kc) {                                                        \
        uint4 v;                                                               \
        v.x = packf16(Brf0.x, Brf1.x);                                         \
        v.y = packf16(Brf0.y, Brf1.y);                                         \
        v.z = packf16(Brf0.z, Brf1.z);                                         \
        v.w = packf16(Brf0.w, Brf1.w);                                         \
        *(uint4*)(Bb[buf] + (tid >> 4) * SB2 + (tid & 15) * 4) = v;            \
        *(uint4*)(stash + ((kc) * 16 + (tid >> 4)) * SB2 + (tid & 15) * 4) = v; }

    // ---- MMA mapping: 8 warps stacked in M; warp tile 32 x 64
    const int lane = tid & 31;
    const int wid = tid >> 5;
    const int wm = wid * 32;
    const int g = lane >> 2, tg = lane & 3;

    float acc[2][8][4];
#pragma unroll
    for (int i = 0; i < 2; ++i)
#pragma unroll
        for (int j = 0; j < 8; ++j)
#pragma unroll
            for (int r = 0; r < 4; ++r) acc[i][j][r] = 0.0f;

    CPA(0, sA0); LD_B(0); ST_B(0, 0);
    asm volatile("cp.async.wait_group 0;");
    __syncthreads();

#pragma unroll
    for (int kc = 0; kc < NCH; ++kc) {
        const int buf = kc & 1;
        if (kc < NCH - 1) { CPA(kc + 1, buf ? sA0 : sA1); LD_B(kc + 1); }

        const uint32_t* A = Ab[buf];
        const uint32_t* B = Bb[buf];
#pragma unroll
        for (int ks = 0; ks < 2; ++ks) {
            const int ko = ks * 8;                 // k2 offset (8 pairs = k16)
            uint32_t a[2][4];
#pragma unroll
            for (int i = 0; i < 2; ++i) {
                const int rb = wm + i * 16 + g;
                a[i][0] = A[(ko + tg) * SA2 + rb];
                a[i][1] = A[(ko + tg) * SA2 + rb + 8];
                a[i][2] = A[(ko + tg + 4) * SA2 + rb];
                a[i][3] = A[(ko + tg + 4) * SA2 + rb + 8];
            }
#pragma unroll
            for (int j = 0; j < 8; ++j) {
                const int cb = j * 8 + g;
                uint32_t b0 = B[(ko + tg) * SB2 + cb];
                uint32_t b1 = B[(ko + tg + 4) * SB2 + cb];
#pragma unroll
                for (int i = 0; i < 2; ++i) mma16(acc[i][j], a[i], b0, b1);
            }
        }
        if (kc < NCH - 1) {
            ST_B(buf ^ 1, kc + 1);
            asm volatile("cp.async.wait_group 0;");
        }
        __syncthreads();
    }

    // ---- fused epilogue: sigmoid + pooled partials; x from fp16 stash
#pragma unroll
    for (int i = 0; i < 2; ++i) {
#pragma unroll
        for (int rs = 0; rs < 2; ++rs) {
            const int lrow = wm + i * 16 + g + rs * 8;      // 0..255
            const int k2L = lrow >> 1, h = lrow & 1;
            const uint32_t* srow = stash + k2L * SB2 + 2 * tg;
            float sS = 0.0f, sP = 0.0f;
#pragma unroll
            for (int j = 0; j < 8; ++j) {
                uint2 u = *(const uint2*)(srow + j * 8);
                __half2 p0 = *reinterpret_cast<__half2*>(&u.x);
                __half2 p1 = *reinterpret_cast<__half2*>(&u.y);
                float xv0 = h ? __high2float(p0) : __low2float(p0);
                float xv1 = h ? __high2float(p1) : __low2float(p1);
                float v0 = acc[i][j][2 * rs];
                float v1 = acc[i][j][2 * rs + 1];
                float s0 = __fdividef(1.0f, 1.0f + __expf(-v0));
                float s1 = __fdividef(1.0f, 1.0f + __expf(-v1));
                sS += s0 + s1;
                sP += s0 * xv0 + s1 * xv1;
            }
            sS += __shfl_xor_sync(0xffffffffu, sS, 1);
            sS += __shfl_xor_sync(0xffffffffu, sS, 2);
            sP += __shfl_xor_sync(0xffffffffu, sP, 1);
            sP += __shfl_xor_sync(0xffffffffu, sP, 2);
            if (tg == 0)
                g_SP[z][lrow][blockIdx.x] = make_float2(sS, sP);
        }
    }
}

// ---------------------------------------------------------------------------
// finalize: 8 threads per output; coalesced float2 reads (32B/thread);
// per-branch divide, then cross-branch add. grid 512 x block 256.
// ---------------------------------------------------------------------------
__global__ void finalize_kernel(float* __restrict__ out) {
    const int tid = threadIdx.x;
    const int i = blockIdx.x * 32 + (tid >> 3);   // output index (b*256+o)
    const int part = tid & 7;                      // br = part>>2, quarter = part&3
    const int b = i >> 8, o = i & 255;
    const int br = part >> 2;
    const int z = br * Bsz + b;
    const int s0 = (part & 3) * 4;

    const float2* p = &g_SP[z][o][s0];
    float2 v0 = p[0], v1 = p[1], v2 = p[2], v3 = p[3];
    float S = (v0.x + v1.x) + (v2.x + v3.x);
    float P = (v0.y + v1.y) + (v2.y + v3.y);
    // reduce the 4 quarters within each branch (lanes differ in bits 0..1)
    S += __shfl_xor_sync(0xffffffffu, S, 1);
    P += __shfl_xor_sync(0xffffffffu, P, 1);
    S += __shfl_xor_sync(0xffffffffu, S, 2);
    P += __shfl_xor_sync(0xffffffffu, P, 2);
    float r = P / (S + 1e-8f);
    // add the two branches (lanes differ in bit 2)
    r += __shfl_xor_sync(0xffffffffu, r, 4);
    if (part == 0) out[i] = r;
}

// ---------------------------------------------------------------------------
extern "C" void kernel_launch(void* const* d_in, const int* in_sizes, int n_in,
                              void* d_out, int out_size) {
    const float* x1 = (const float*)d_in[0];
    const float* x2 = (const float*)d_in[1];
    const float* w  = (const float*)d_in[2];
    // d_in[3..6] (ca_*) are mathematically unused: softmax over a size-1 axis == 1.
    float* out = (float*)d_out;

    constexpr int SMEM_SZ = (2 * BUFA + 2 * BUFB + 128 * SB2) * 4;   // 79872 B
    cudaFuncSetAttribute(gemm_pool_kernel,
                         cudaFuncAttributeMaxDynamicSharedMemorySize, SMEM_SZ);

    transpose_w<<<64, 1024>>>(w);
    build_wzh<<<dim3(32, 2 * Bsz), 1024>>>(x1, x2);
    gemm_pool_kernel<<<dim3(16, 2 * Bsz), 256, SMEM_SZ>>>(x1, x2);
    finalize_kernel<<<512, 256>>>(out);
}

// round 15
// speedup vs baseline: 1.2935x; 1.1579x over previous
#include <cuda_runtime.h>
#include <cuda_fp16.h>
#include <cstdint>

#define Bsz  64
#define Csz  256
#define HW   1024
#define CTR  528        // 16*32 + 16
#define KC   32         // K chunk (= 16 fp16x2 k-pairs)
#define NCH  8          // 256 / 32
#define SA2  264        // A smem k2-row stride (u32): 256 + 8
#define SB2  72         // B smem k2-row stride (u32): 64 + 8
#define BUFA (16 * SA2) // 4224 u32
#define BUFB (16 * SB2) // 1152 u32

// per-CTA partials: [z][ntile][o]  (R11 layout, coalesced epilogue stores)
__device__ float g_S[2 * Bsz][16][Csz];
__device__ float g_P[2 * Bsz][16][Csz];

// per-z folded A operand packed as fp16x2 over k-pairs
__device__ uint32_t g_Wzh[2 * Bsz][Csz / 2][Csz];   // 16.8 MB (L2-resident)

__device__ __forceinline__ uint32_t packf16(float lo, float hi) {
    uint32_t d;
    asm("cvt.rn.f16x2.f32 %0, %1, %2;" : "=r"(d) : "f"(hi), "f"(lo));
    return d;
}

__device__ __forceinline__ void mma16(float* c, const uint32_t* a,
                                      uint32_t b0, uint32_t b1) {
    asm volatile(
        "mma.sync.aligned.m16n8k16.row.col.f32.f16.f16.f32 "
        "{%0,%1,%2,%3}, {%4,%5,%6,%7}, {%8,%9}, {%0,%1,%2,%3};"
        : "+f"(c[0]), "+f"(c[1]), "+f"(c[2]), "+f"(c[3])
        : "r"(a[0]), "r"(a[1]), "r"(a[2]), "r"(a[3]), "r"(b0), "r"(b1));
}

__device__ __forceinline__ uint32_t smem_u32(const void* p) {
    uint32_t a;
    asm("{ .reg .u64 t; cvta.to.shared.u64 t, %1; cvt.u32.u64 %0, t; }" : "=r"(a) : "l"(p));
    return a;
}

// ---------------------------------------------------------------------------
// fused prep: Wzh[z][k2][m] = fp16x2(W[m][2k2]   + W[m][256]*cen_z(2k2),
//                                    W[m][2k2+1] + W[m][256]*cen_z(2k2+1))
// W transposed through smem (coalesced loads; stride-257 tile = conflict-free)
// grid (8 k-tiles, 128 z), block 1024
// ---------------------------------------------------------------------------
__global__ void __launch_bounds__(1024)
build_wzh(const float* __restrict__ x1, const float* __restrict__ x2,
          const float* __restrict__ w) {
    __shared__ float wt[32][257];   // [kk][m]; (kk*257+m)%32 = (kk+m)%32
    __shared__ float wc[256];
    __shared__ float cen[32];

    const int z = blockIdx.y;
    const int branch = z >> 6, b = z & 63;
    const float* xz = (branch ? x2 : x1) + (size_t)b * Csz * HW;
    const int k0 = blockIdx.x * 32;
    const int tid = threadIdx.x;

    // load 32k x 256m W tile; per-warp: one m-row, 32 consecutive k (128 B)
#pragma unroll
    for (int q = 0; q < 8; ++q) {
        int e = tid + q * 1024;
        int m = e >> 5, kk = e & 31;
        wt[kk][m] = w[(size_t)m * 257 + k0 + kk];
    }
    if (tid < 256) wc[tid] = w[(size_t)tid * 257 + 256];
    if (tid < 32)  cen[tid] = xz[(size_t)(k0 + tid) * HW + CTR] * (1.0f / 256.0f);
    __syncthreads();

    // emit folded fp16x2, m-major coalesced
#pragma unroll
    for (int q = 0; q < 4; ++q) {
        int e = tid + q * 1024;
        int m = e & 255, k2l = e >> 8;                 // k2l 0..15
        float wcm = wc[m];
        float v0 = wt[2 * k2l][m]     + wcm * cen[2 * k2l];
        float v1 = wt[2 * k2l + 1][m] + wcm * cen[2 * k2l + 1];
        g_Wzh[z][(k0 >> 1) + k2l][m] = packf16(v0, v1);
    }
}

// ---------------------------------------------------------------------------
// main GEMM (fp16 in, fp32 acc) + fused sigmoid-pool  (R11, verbatim)
// grid (16 n-tiles, 128 z), block 256 (8 warps = 8M x 1N; warp tile 32 x 64)
// ---------------------------------------------------------------------------
__global__ void __launch_bounds__(256, 2)
gemm_pool_kernel(const float* __restrict__ x1, const float* __restrict__ x2) {
    extern __shared__ uint32_t sm[];
    uint32_t* Ab[2] = { sm, sm + BUFA };
    uint32_t* Bb[2] = { sm + 2 * BUFA, sm + 2 * BUFA + BUFB };
    uint32_t* stash = sm + 2 * BUFA + 2 * BUFB;   // 128 k2-rows x SB2

    const int tid = threadIdx.x;
    const int z = blockIdx.y;
    const int branch = z >> 6, b = z & 63;
    const float* xz = (branch ? x2 : x1) + (size_t)b * Csz * HW;
    const int n0 = blockIdx.x * 64;
    const uint32_t* wzh = &g_Wzh[z][0][0];        // [128 k2][256 m]

    const uint32_t sA0 = smem_u32(Ab[0]);
    const uint32_t sA1 = smem_u32(Ab[1]);

    float4 Brf0, Brf1;

#define CPA(kc, sbase) { _Pragma("unroll") for (int q = 0; q < 4; ++q) {       \
        int idx = tid + q * 256;                                               \
        uint32_t dst = (sbase) + ((idx >> 6) * SA2 + (idx & 63) * 4) * 4;      \
        const uint32_t* src = wzh + (size_t)((kc) * 16 + (idx >> 6)) * 256     \
                              + (idx & 63) * 4;                                \
        asm volatile("cp.async.cg.shared.global [%0], [%1], 16;"               \
                     :: "r"(dst), "l"(src)); }                                 \
    asm volatile("cp.async.commit_group;"); }
#define LD_B(kc) {                                                             \
        const float* p0 = xz + (size_t)((kc) * KC + 2 * (tid >> 4)) * HW       \
                          + n0 + (tid & 15) * 4;                               \
        Brf0 = *(const float4*)p0;                                             \
        Brf1 = *(const float4*)(p0 + HW); }
#define ST_B(buf, kc) {                                                        \
        uint4 v;                                                               \
        v.x = packf16(Brf0.x, Brf1.x);                                         \
        v.y = packf16(Brf0.y, Brf1.y);                                         \
        v.z = packf16(Brf0.z, Brf1.z);                                         \
        v.w = packf16(Brf0.w, Brf1.w);                                         \
        *(uint4*)(Bb[buf] + (tid >> 4) * SB2 + (tid & 15) * 4) = v;            \
        *(uint4*)(stash + ((kc) * 16 + (tid >> 4)) * SB2 + (tid & 15) * 4) = v; }

    // ---- MMA mapping: 8 warps stacked in M; warp tile 32 x 64
    const int lane = tid & 31;
    const int wid = tid >> 5;
    const int wm = wid * 32;
    const int g = lane >> 2, tg = lane & 3;

    float acc[2][8][4];
#pragma unroll
    for (int i = 0; i < 2; ++i)
#pragma unroll
        for (int j = 0; j < 8; ++j)
#pragma unroll
            for (int r = 0; r < 4; ++r) acc[i][j][r] = 0.0f;

    CPA(0, sA0); LD_B(0); ST_B(0, 0);
    asm volatile("cp.async.wait_group 0;");
    __syncthreads();

#pragma unroll
    for (int kc = 0; kc < NCH; ++kc) {
        const int buf = kc & 1;
        if (kc < NCH - 1) { CPA(kc + 1, buf ? sA0 : sA1); LD_B(kc + 1); }

        const uint32_t* A = Ab[buf];
        const uint32_t* B = Bb[buf];
#pragma unroll
        for (int ks = 0; ks < 2; ++ks) {
            const int ko = ks * 8;                 // k2 offset (8 pairs = k16)
            uint32_t a[2][4];
#pragma unroll
            for (int i = 0; i < 2; ++i) {
                const int rb = wm + i * 16 + g;
                a[i][0] = A[(ko + tg) * SA2 + rb];
                a[i][1] = A[(ko + tg) * SA2 + rb + 8];
                a[i][2] = A[(ko + tg + 4) * SA2 + rb];
                a[i][3] = A[(ko + tg + 4) * SA2 + rb + 8];
            }
#pragma unroll
            for (int j = 0; j < 8; ++j) {
                const int cb = j * 8 + g;
                uint32_t b0 = B[(ko + tg) * SB2 + cb];
                uint32_t b1 = B[(ko + tg + 4) * SB2 + cb];
#pragma unroll
                for (int i = 0; i < 2; ++i) mma16(acc[i][j], a[i], b0, b1);
            }
        }
        if (kc < NCH - 1) {
            ST_B(buf ^ 1, kc + 1);
            asm volatile("cp.async.wait_group 0;");
        }
        __syncthreads();
    }

    // ---- fused epilogue: sigmoid + pooled partials; x from fp16 stash
#pragma unroll
    for (int i = 0; i < 2; ++i) {
#pragma unroll
        for (int rs = 0; rs < 2; ++rs) {
            const int lrow = wm + i * 16 + g + rs * 8;      // 0..255
            const int k2L = lrow >> 1, h = lrow & 1;
            const uint32_t* srow = stash + k2L * SB2 + 2 * tg;
            float sS = 0.0f, sP = 0.0f;
#pragma unroll
            for (int j = 0; j < 8; ++j) {
                uint2 u = *(const uint2*)(srow + j * 8);
                __half2 p0 = *reinterpret_cast<__half2*>(&u.x);
                __half2 p1 = *reinterpret_cast<__half2*>(&u.y);
                float xv0 = h ? __high2float(p0) : __low2float(p0);
                float xv1 = h ? __high2float(p1) : __low2float(p1);
                float v0 = acc[i][j][2 * rs];
                float v1 = acc[i][j][2 * rs + 1];
                float s0 = __fdividef(1.0f, 1.0f + __expf(-v0));
                float s1 = __fdividef(1.0f, 1.0f + __expf(-v1));
                sS += s0 + s1;
                sP += s0 * xv0 + s1 * xv1;
            }
            sS += __shfl_xor_sync(0xffffffffu, sS, 1);
            sS += __shfl_xor_sync(0xffffffffu, sS, 2);
            sP += __shfl_xor_sync(0xffffffffu, sP, 1);
            sP += __shfl_xor_sync(0xffffffffu, sP, 2);
            if (tg == 0) {
                g_S[z][blockIdx.x][lrow] = sS;
                g_P[z][blockIdx.x][lrow] = sP;
            }
        }
    }
}

// ---------------------------------------------------------------------------
// finalize (R11, verbatim): 8 threads per output; per-branch divide, then
// cross-branch add. grid 512 x block 256 -> 32 outputs/block
// ---------------------------------------------------------------------------
__global__ void finalize_kernel(float* __restrict__ out) {
    const int tid = threadIdx.x;
    const int i = blockIdx.x * 32 + (tid >> 3);   // output index (b*256+o)
    const int part = tid & 7;                      // br = part>>2, quarter = part&3
    const int b = i >> 8, o = i & 255;
    const int br = part >> 2;
    const int z = br * Bsz + b;
    const int s0 = (part & 3) * 4;

    float S = (g_S[z][s0][o] + g_S[z][s0 + 1][o])
            + (g_S[z][s0 + 2][o] + g_S[z][s0 + 3][o]);
    float P = (g_P[z][s0][o] + g_P[z][s0 + 1][o])
            + (g_P[z][s0 + 2][o] + g_P[z][s0 + 3][o]);
    // reduce the 4 quarters within each branch (lanes differ in bits 0..1)
    S += __shfl_xor_sync(0xffffffffu, S, 1);
    P += __shfl_xor_sync(0xffffffffu, P, 1);
    S += __shfl_xor_sync(0xffffffffu, S, 2);
    P += __shfl_xor_sync(0xffffffffu, P, 2);
    float r = P / (S + 1e-8f);
    // add the two branches (lanes differ in bit 2)
    r += __shfl_xor_sync(0xffffffffu, r, 4);
    if (part == 0) out[i] = r;
}

// ---------------------------------------------------------------------------
extern "C" void kernel_launch(void* const* d_in, const int* in_sizes, int n_in,
                              void* d_out, int out_size) {
    const float* x1 = (const float*)d_in[0];
    const float* x2 = (const float*)d_in[1];
    const float* w  = (const float*)d_in[2];
    // d_in[3..6] (ca_*) are mathematically unused: softmax over a size-1 axis == 1.
    float* out = (float*)d_out;

    constexpr int SMEM_SZ = (2 * BUFA + 2 * BUFB + 128 * SB2) * 4;   // 79872 B
    cudaFuncSetAttribute(gemm_pool_kernel,
                         cudaFuncAttributeMaxDynamicSharedMemorySize, SMEM_SZ);

    build_wzh<<<dim3(8, 2 * Bsz), 1024>>>(x1, x2, w);
    gemm_pool_kernel<<<dim3(16, 2 * Bsz), 256, SMEM_SZ>>>(x1, x2);
    finalize_kernel<<<512, 256>>>(out);
}

// round 16
// speedup vs baseline: 1.3557x; 1.0480x over previous
#include <cuda_runtime.h>
#include <cuda_fp16.h>
#include <cstdint>

#define Bsz  64
#define Csz  256
#define HW   1024
#define CTR  528        // 16*32 + 16
#define KC   32         // K chunk (= 16 fp16x2 k-pairs)
#define NCH  8          // 256 / 32
#define SA2  264        // A smem k2-row stride (u32): 256 + 8
#define SB2  72         // B smem k2-row stride (u32): 64 + 8
#define BUFA (16 * SA2) // 4224 u32
#define BUFB (16 * SB2) // 1152 u32

// per-CTA partials: [z][ntile][o]
__device__ float g_S[2 * Bsz][16][Csz];
__device__ float g_P[2 * Bsz][16][Csz];

// per-z folded A operand packed as fp16x2 over k-pairs
__device__ uint32_t g_Wzh[2 * Bsz][Csz / 2][Csz];   // 16.8 MB (L2-resident)

__device__ __forceinline__ uint32_t packf16(float lo, float hi) {
    uint32_t d;
    asm("cvt.rn.f16x2.f32 %0, %1, %2;" : "=r"(d) : "f"(hi), "f"(lo));
    return d;
}

__device__ __forceinline__ void mma16(float* c, const uint32_t* a,
                                      uint32_t b0, uint32_t b1) {
    asm volatile(
        "mma.sync.aligned.m16n8k16.row.col.f32.f16.f16.f32 "
        "{%0,%1,%2,%3}, {%4,%5,%6,%7}, {%8,%9}, {%0,%1,%2,%3};"
        : "+f"(c[0]), "+f"(c[1]), "+f"(c[2]), "+f"(c[3])
        : "r"(a[0]), "r"(a[1]), "r"(a[2]), "r"(a[3]), "r"(b0), "r"(b1));
}

__device__ __forceinline__ uint32_t smem_u32(const void* p) {
    uint32_t a;
    asm("{ .reg .u64 t; cvta.to.shared.u64 t, %1; cvt.u32.u64 %0, t; }" : "=r"(a) : "l"(p));
    return a;
}

// ---------------------------------------------------------------------------
// fused prep, z-amortized: each block folds one 32-k tile for 8 z values.
// Wzh[z][k2][m] = fp16x2(W[m][2k2]   + W[m][256]*cen_z(2k2),
//                        W[m][2k2+1] + W[m][256]*cen_z(2k2+1))
// grid (8 k-tiles, 16 z-groups), block 1024
// ---------------------------------------------------------------------------
__global__ void __launch_bounds__(1024)
build_wzh(const float* __restrict__ x1, const float* __restrict__ x2,
          const float* __restrict__ w) {
    __shared__ float wt[32][257];     // [kk][m]; stride 257 -> conflict-free
    __shared__ float wc_s[256];
    __shared__ float cen_s[8][32];

    const int k0 = blockIdx.x * 32;
    const int zg = blockIdx.y * 8;
    const int tid = threadIdx.x;

    // W tile: per-warp one m-row, 32 consecutive k (coalesced 128 B)
#pragma unroll
    for (int q = 0; q < 8; ++q) {
        int e = tid + q * 1024;
        int m = e >> 5, kk = e & 31;
        wt[kk][m] = w[(size_t)m * 257 + k0 + kk];
    }
    if (tid < 256) {
        // cen for 8 z values (scattered, once per block)
        int zi = tid >> 5, kk = tid & 31;
        int z = zg + zi;
        const float* xz = ((z >> 6) ? x2 : x1) + (size_t)(z & 63) * Csz * HW;
        cen_s[zi][kk] = xz[(size_t)(k0 + kk) * HW + CTR] * (1.0f / 256.0f);
    } else if (tid < 512) {
        int m = tid - 256;
        wc_s[m] = w[(size_t)m * 257 + 256];
    }
    __syncthreads();

    // fixed slice per thread: k2l = tid>>6 (0..15), m4 = (tid&63)*4
    const int k2l = tid >> 6;
    const int m4 = (tid & 63) * 4;
    float wt0[4], wt1[4], wc4[4];
#pragma unroll
    for (int i = 0; i < 4; ++i) {
        wt0[i] = wt[2 * k2l][m4 + i];
        wt1[i] = wt[2 * k2l + 1][m4 + i];
        wc4[i] = wc_s[m4 + i];
    }

    const int k2 = (k0 >> 1) + k2l;
#pragma unroll
    for (int zi = 0; zi < 8; ++zi) {
        const int z = zg + zi;
        const float c0 = cen_s[zi][2 * k2l];       // warp-broadcast
        const float c1 = cen_s[zi][2 * k2l + 1];
        uint4 v;
        v.x = packf16(wt0[0] + wc4[0] * c0, wt1[0] + wc4[0] * c1);
        v.y = packf16(wt0[1] + wc4[1] * c0, wt1[1] + wc4[1] * c1);
        v.z = packf16(wt0[2] + wc4[2] * c0, wt1[2] + wc4[2] * c1);
        v.w = packf16(wt0[3] + wc4[3] * c0, wt1[3] + wc4[3] * c1);
        *(uint4*)&g_Wzh[z][k2][m4] = v;            // coalesced 16 B
    }
}

// ---------------------------------------------------------------------------
// main GEMM (fp16 in, fp32 acc) + fused sigmoid-pool  (R11/R15, verbatim)
// grid (16 n-tiles, 128 z), block 256 (8 warps = 8M x 1N; warp tile 32 x 64)
// ---------------------------------------------------------------------------
__global__ void __launch_bounds__(256, 2)
gemm_pool_kernel(const float* __restrict__ x1, const float* __restrict__ x2) {
    extern __shared__ uint32_t sm[];
    uint32_t* Ab[2] = { sm, sm + BUFA };
    uint32_t* Bb[2] = { sm + 2 * BUFA, sm + 2 * BUFA + BUFB };
    uint32_t* stash = sm + 2 * BUFA + 2 * BUFB;   // 128 k2-rows x SB2

    const int tid = threadIdx.x;
    const int z = blockIdx.y;
    const int branch = z >> 6, b = z & 63;
    const float* xz = (branch ? x2 : x1) + (size_t)b * Csz * HW;
    const int n0 = blockIdx.x * 64;
    const uint32_t* wzh = &g_Wzh[z][0][0];        // [128 k2][256 m]

    const uint32_t sA0 = smem_u32(Ab[0]);
    const uint32_t sA1 = smem_u32(Ab[1]);

    float4 Brf0, Brf1;

#define CPA(kc, sbase) { _Pragma("unroll") for (int q = 0; q < 4; ++q) {       \
        int idx = tid + q * 256;                                               \
        uint32_t dst = (sbase) + ((idx >> 6) * SA2 + (idx & 63) * 4) * 4;      \
        const uint32_t* src = wzh + (size_t)((kc) * 16 + (idx >> 6)) * 256     \
                              + (idx & 63) * 4;                                \
        asm volatile("cp.async.cg.shared.global [%0], [%1], 16;"               \
                     :: "r"(dst), "l"(src)); }                                 \
    asm volatile("cp.async.commit_group;"); }
#define LD_B(kc) {                                                             \
        const float* p0 = xz + (size_t)((kc) * KC + 2 * (tid >> 4)) * HW       \
                          + n0 + (tid & 15) * 4;                               \
        Brf0 = *(const float4*)p0;                                             \
        Brf1 = *(const float4*)(p0 + HW); }
#define ST_B(buf, kc) {                                                        \
        uint4 v;                                                               \
        v.x = packf16(Brf0.x, Brf1.x);                                         \
        v.y = packf16(Brf0.y, Brf1.y);                                         \
        v.z = packf16(Brf0.z, Brf1.z);                                         \
        v.w = packf16(Brf0.w, Brf1.w);                                         \
        *(uint4*)(Bb[buf] + (tid >> 4) * SB2 + (tid & 15) * 4) = v;            \
        *(uint4*)(stash + ((kc) * 16 + (tid >> 4)) * SB2 + (tid & 15) * 4) = v; }

    // ---- MMA mapping: 8 warps stacked in M; warp tile 32 x 64
    const int lane = tid & 31;
    const int wid = tid >> 5;
    const int wm = wid * 32;
    const int g = lane >> 2, tg = lane & 3;

    float acc[2][8][4];
#pragma unroll
    for (int i = 0; i < 2; ++i)
#pragma unroll
        for (int j = 0; j < 8; ++j)
#pragma unroll
            for (int r = 0; r < 4; ++r) acc[i][j][r] = 0.0f;

    CPA(0, sA0); LD_B(0); ST_B(0, 0);
    asm volatile("cp.async.wait_group 0;");
    __syncthreads();

#pragma unroll
    for (int kc = 0; kc < NCH; ++kc) {
        const int buf = kc & 1;
        if (kc < NCH - 1) { CPA(kc + 1, buf ? sA0 : sA1); LD_B(kc + 1); }

        const uint32_t* A = Ab[buf];
        const uint32_t* B = Bb[buf];
#pragma unroll
        for (int ks = 0; ks < 2; ++ks) {
            const int ko = ks * 8;                 // k2 offset (8 pairs = k16)
            uint32_t a[2][4];
#pragma unroll
            for (int i = 0; i < 2; ++i) {
                const int rb = wm + i * 16 + g;
                a[i][0] = A[(ko + tg) * SA2 + rb];
                a[i][1] = A[(ko + tg) * SA2 + rb + 8];
                a[i][2] = A[(ko + tg + 4) * SA2 + rb];
                a[i][3] = A[(ko + tg + 4) * SA2 + rb + 8];
            }
#pragma unroll
            for (int j = 0; j < 8; ++j) {
                const int cb = j * 8 + g;
                uint32_t b0 = B[(ko + tg) * SB2 + cb];
                uint32_t b1 = B[(ko + tg + 4) * SB2 + cb];
#pragma unroll
                for (int i = 0; i < 2; ++i) mma16(acc[i][j], a[i], b0, b1);
            }
        }
        if (kc < NCH - 1) {
            ST_B(buf ^ 1, kc + 1);
            asm volatile("cp.async.wait_group 0;");
        }
        __syncthreads();
    }

    // ---- fused epilogue: sigmoid + pooled partials; x from fp16 stash
#pragma unroll
    for (int i = 0; i < 2; ++i) {
#pragma unroll
        for (int rs = 0; rs < 2; ++rs) {
            const int lrow = wm + i * 16 + g + rs * 8;      // 0..255
            const int k2L = lrow >> 1, h = lrow & 1;
            const uint32_t* srow = stash + k2L * SB2 + 2 * tg;
            float sS = 0.0f, sP = 0.0f;
#pragma unroll
            for (int j = 0; j < 8; ++j) {
                uint2 u = *(const uint2*)(srow + j * 8);
                __half2 p0 = *reinterpret_cast<__half2*>(&u.x);
                __half2 p1 = *reinterpret_cast<__half2*>(&u.y);
                float xv0 = h ? __high2float(p0) : __low2float(p0);
                float xv1 = h ? __high2float(p1) : __low2float(p1);
                float v0 = acc[i][j][2 * rs];
                float v1 = acc[i][j][2 * rs + 1];
                float s0 = __fdividef(1.0f, 1.0f + __expf(-v0));
                float s1 = __fdividef(1.0f, 1.0f + __expf(-v1));
                sS += s0 + s1;
                sP += s0 * xv0 + s1 * xv1;
            }
            sS += __shfl_xor_sync(0xffffffffu, sS, 1);
            sS += __shfl_xor_sync(0xffffffffu, sS, 2);
            sP += __shfl_xor_sync(0xffffffffu, sP, 1);
            sP += __shfl_xor_sync(0xffffffffu, sP, 2);
            if (tg == 0) {
                g_S[z][blockIdx.x][lrow] = sS;
                g_P[z][blockIdx.x][lrow] = sP;
            }
        }
    }
}

// ---------------------------------------------------------------------------
// finalize (verbatim): 8 threads per output; per-branch divide, then
// cross-branch add. grid 512 x block 256 -> 32 outputs/block
// ---------------------------------------------------------------------------
__global__ void finalize_kernel(float* __restrict__ out) {
    const int tid = threadIdx.x;
    const int i = blockIdx.x * 32 + (tid >> 3);   // output index (b*256+o)
    const int part = tid & 7;                      // br = part>>2, quarter = part&3
    const int b = i >> 8, o = i & 255;
    const int br = part >> 2;
    const int z = br * Bsz + b;
    const int s0 = (part & 3) * 4;

    float S = (g_S[z][s0][o] + g_S[z][s0 + 1][o])
            + (g_S[z][s0 + 2][o] + g_S[z][s0 + 3][o]);
    float P = (g_P[z][s0][o] + g_P[z][s0 + 1][o])
            + (g_P[z][s0 + 2][o] + g_P[z][s0 + 3][o]);
    // reduce the 4 quarters within each branch (lanes differ in bits 0..1)
    S += __shfl_xor_sync(0xffffffffu, S, 1);
    P += __shfl_xor_sync(0xffffffffu, P, 1);
    S += __shfl_xor_sync(0xffffffffu, S, 2);
    P += __shfl_xor_sync(0xffffffffu, P, 2);
    float r = P / (S + 1e-8f);
    // add the two branches (lanes differ in bit 2)
    r += __shfl_xor_sync(0xffffffffu, r, 4);
    if (part == 0) out[i] = r;
}

// ---------------------------------------------------------------------------
extern "C" void kernel_launch(void* const* d_in, const int* in_sizes, int n_in,
                              void* d_out, int out_size) {
    const float* x1 = (const float*)d_in[0];
    const float* x2 = (const float*)d_in[1];
    const float* w  = (const float*)d_in[2];
    // d_in[3..6] (ca_*) are mathematically unused: softmax over a size-1 axis == 1.
    float* out = (float*)d_out;

    constexpr int SMEM_SZ = (2 * BUFA + 2 * BUFB + 128 * SB2) * 4;   // 79872 B
    cudaFuncSetAttribute(gemm_pool_kernel,
                         cudaFuncAttributeMaxDynamicSharedMemorySize, SMEM_SZ);

    build_wzh<<<dim3(8, 16), 1024>>>(x1, x2, w);
    gemm_pool_kernel<<<dim3(16, 2 * Bsz), 256, SMEM_SZ>>>(x1, x2);
    finalize_kernel<<<512, 256>>>(out);
}